// round 9
// baseline (speedup 1.0000x reference)
#include <cuda_runtime.h>
#include <cuda_fp16.h>
#include <math.h>
#include <stdint.h>

#define SEQ 2048
#define DM  1024
#define NB  4

static constexpr size_t NQ  = (size_t)NB * SEQ * DM;    //  8388608
static constexpr size_t NSS = (size_t)NB * SEQ * SEQ;   // 16777216
static constexpr size_t NP  = (size_t)SEQ * DM;         //  2097152
static constexpr size_t NU  = (size_t)DM * DM;          //  1048576

// ---- scratch (static device globals; no allocation) ----
__device__ int8_t g_qh[NQ],  g_ql[NQ];
__device__ int8_t g_kh[NQ],  g_kl[NQ];
__device__ int8_t g_vth[NQ], g_vtl[NQ];
__device__ int8_t g_eh[NSS], g_el[NSS];
__device__ float  g_rscale[(size_t)NB * SEQ];
__device__ __half g_pehi[NP];
__device__ __half g_uqt[NU],  g_ukt[NU];
__device__ __half g_qpe[NP],  g_kpe[NP];
__device__ float  g_bias[(size_t)SEQ * SEQ];
__device__ float  g_scores[NSS];

static constexpr float SPLIT_SCALE = 127.0f / 6.0f;        // fp32 -> int8-pair scale
static constexpr float INV_SPLIT2  = (6.0f / 127.0f) * (6.0f / 127.0f);

// ------------------------------- PTX helpers -------------------------------
__device__ __forceinline__ uint32_t s2u(const void* p) {
    uint32_t a;
    asm("{ .reg .u64 t; cvta.to.shared.u64 t, %1; cvt.u32.u64 %0, t; }"
        : "=r"(a) : "l"(p));
    return a;
}
__device__ __forceinline__ void cpa16(uint32_t dst, const void* src) {
    asm volatile("cp.async.cg.shared.global [%0], [%1], 16;" :: "r"(dst), "l"(src) : "memory");
}
#define LDSM4(r, addr) \
    asm volatile("ldmatrix.sync.aligned.m8n8.x4.shared.b16 {%0,%1,%2,%3}, [%4];" \
        : "=r"((r)[0]), "=r"((r)[1]), "=r"((r)[2]), "=r"((r)[3]) : "r"(addr))
#define MMA_F16_F32(d, a, b0, b1) \
    asm volatile("mma.sync.aligned.m16n8k16.row.col.f32.f16.f16.f32 " \
        "{%0,%1,%2,%3}, {%4,%5,%6,%7}, {%8,%9}, {%0,%1,%2,%3};" \
        : "+f"((d)[0]), "+f"((d)[1]), "+f"((d)[2]), "+f"((d)[3]) \
        : "r"((a)[0]), "r"((a)[1]), "r"((a)[2]), "r"((a)[3]), "r"(b0), "r"(b1))
#define MMA_S8(d, a, b0, b1) \
    asm volatile("mma.sync.aligned.m16n8k32.row.col.s32.s8.s8.s32 " \
        "{%0,%1,%2,%3}, {%4,%5,%6,%7}, {%8,%9}, {%0,%1,%2,%3};" \
        : "+r"((d)[0]), "+r"((d)[1]), "+r"((d)[2]), "+r"((d)[3]) \
        : "r"((a)[0]), "r"((a)[1]), "r"((a)[2]), "r"((a)[3]), "r"(b0), "r"(b1))

// ---------------------------------------------------------------------------
// int8 IMMA GEMM with two-digit operands:
//   A ~ s_a(Ah + Al/254), B ~ s_b(Bh + Bl/254), int8 digit matrices, K-major.
//   main = Ah@Bh^T; cross = Ah@Bl^T + Al@Bh^T; (LOLO) ll = Al@Bl^T  (s32 exact)
//   MODE 0 (scores): C = alpha*(main + cross/254 [+ ll/254^2]) + bias*beta
//   MODE 1 (ctx)   : C = alpha*(main + cross/254 [+ ll/254^2]) * rscale[bz*Ng+n]
// CTA tile 128x64, BK=64 int8, 256 threads, 8 warps (4 M x 2 N, warp 32x32),
// 2-stage cp.async pipeline, 80B-padded SMEM rows.
// ---------------------------------------------------------------------------
template<int MODE, int LOLO>
__global__ void __launch_bounds__(256, 1)
igemm(const int8_t* __restrict__ Ah, const int8_t* __restrict__ Al,
      const int8_t* __restrict__ Bh, const int8_t* __restrict__ Bl,
      float* __restrict__ C, const float* __restrict__ bias,
      const float* __restrict__ rscale, int Kt, int Ng,
      long long aStr, long long bStr, long long cStr, float alpha, float beta)
{
    extern __shared__ __align__(128) char smem[];
    constexpr int RSTR = 80;
    constexpr int TSA = 128 * RSTR;             // A digit tile: 10240 B
    constexpr int TSB = 64 * RSTR;              // B digit tile:  5120 B
    constexpr int STAGE = 2 * TSA + 2 * TSB;    // 30720 B

    const uint32_t sb = s2u(smem);
    const int tid = threadIdx.x;
    const int lane = tid & 31;
    const int wid = tid >> 5;
    const int warp_m = wid & 3;                 // 4 warps along M (32 rows each)
    const int warp_n = wid >> 2;                // 2 warps along N (32 cols each)
    const int bm = blockIdx.y * 128, bn = blockIdx.x * 64, bz = blockIdx.z;
    const int NC = Kt >> 6;                     // chunks of 64 int8

    const int8_t* Abase[2] = { Ah + (long long)bz * aStr, Al + (long long)bz * aStr };
    const int8_t* Bbase[2] = { Bh + (long long)bz * bStr, Bl + (long long)bz * bStr };

    auto load_chunk = [&](int c) {
        const uint32_t stg = sb + (c & 1) * STAGE;
        const long long kc = (long long)c << 6;
        #pragma unroll
        for (int it = 0; it < 6; it++) {
            const int idx = tid + it * 256;     // 1536 chunks of 16B
            uint32_t dst; const int8_t* src;
            const int c16 = idx & 3;
            if (idx < 1024) {                   // A tiles: 2 x 128 rows x 4
                const int t4 = idx >> 9;
                const int r  = (idx >> 2) & 127;
                dst = stg + t4 * TSA + r * RSTR + c16 * 16;
                src = Abase[t4] + (long long)(bm + r) * Kt + kc + c16 * 16;
            } else {                            // B tiles: 2 x 64 rows x 4
                const int j  = idx - 1024;
                const int t4 = j >> 8;
                const int r  = (j >> 2) & 63;
                dst = stg + 2 * TSA + t4 * TSB + r * RSTR + c16 * 16;
                src = Bbase[t4] + (long long)(bn + r) * Kt + kc + c16 * 16;
            }
            cpa16(dst, src);
        }
        asm volatile("cp.async.commit_group;" ::: "memory");
    };

    int accm[2][4][4], accx[2][4][4], accl[2][4][4];
    #pragma unroll
    for (int f = 0; f < 2; f++)
        #pragma unroll
        for (int j = 0; j < 4; j++)
            #pragma unroll
            for (int e = 0; e < 4; e++) {
                accm[f][j][e] = 0; accx[f][j][e] = 0;
                if (LOLO) accl[f][j][e] = 0;
            }

    load_chunk(0);

    const int lrow = lane & 15;
    const int lkof = (lane >> 4) * 16;

    for (int c = 0; c < NC; c++) {
        if (c + 1 < NC) {
            load_chunk(c + 1);
            asm volatile("cp.async.wait_group 1;" ::: "memory");
        } else {
            asm volatile("cp.async.wait_group 0;" ::: "memory");
        }
        __syncthreads();
        const uint32_t stg = sb + (c & 1) * STAGE;
        const uint32_t aOff = stg + (warp_m * 32 + lrow) * RSTR + lkof;
        const uint32_t bOff = stg + 2 * TSA + (warp_n * 32 + lrow) * RSTR + lkof;
        #pragma unroll
        for (int ks = 0; ks < 2; ks++) {        // two k32 steps per 64B row
            const uint32_t kb = ks * 32;
            uint32_t ah[2][4], al[2][4], bh[2][4], bl[2][4];
            #pragma unroll
            for (int f = 0; f < 2; f++) {
                LDSM4(ah[f], aOff + f * 16 * RSTR + kb);
                LDSM4(al[f], aOff + TSA + f * 16 * RSTR + kb);
            }
            #pragma unroll
            for (int g = 0; g < 2; g++) {
                LDSM4(bh[g], bOff + g * 16 * RSTR + kb);
                LDSM4(bl[g], bOff + TSB + g * 16 * RSTR + kb);
            }
            #pragma unroll
            for (int f = 0; f < 2; f++)
                #pragma unroll
                for (int g = 0; g < 2; g++)
                    #pragma unroll
                    for (int h = 0; h < 2; h++) {
                        const int j = g * 2 + h;
                        MMA_S8(accm[f][j], ah[f], bh[g][h], bh[g][h + 2]);
                        MMA_S8(accx[f][j], ah[f], bl[g][h], bl[g][h + 2]);
                        MMA_S8(accx[f][j], al[f], bh[g][h], bh[g][h + 2]);
                        if (LOLO)
                            MMA_S8(accl[f][j], al[f], bl[g][h], bl[g][h + 2]);
                    }
        }
        __syncthreads();
    }

    // ------------------------------- epilogue -------------------------------
    const float a2 = alpha * (1.0f / 254.0f);
    const float a3 = alpha * (1.0f / (254.0f * 254.0f));
    const int qrow = lane >> 2;
    const int qcol = (lane & 3) * 2;
    float* Cf = C + (long long)bz * cStr;
    #pragma unroll
    for (int f = 0; f < 2; f++) {
        const int m0 = bm + warp_m * 32 + f * 16 + qrow;
        #pragma unroll
        for (int j = 0; j < 4; j++) {
            const int n = bn + warp_n * 32 + j * 8 + qcol;
            float e0 = (float)accm[f][j][0] * alpha + (float)accx[f][j][0] * a2;
            float e1 = (float)accm[f][j][1] * alpha + (float)accx[f][j][1] * a2;
            float e2 = (float)accm[f][j][2] * alpha + (float)accx[f][j][2] * a2;
            float e3 = (float)accm[f][j][3] * alpha + (float)accx[f][j][3] * a2;
            if (LOLO) {
                e0 += (float)accl[f][j][0] * a3; e1 += (float)accl[f][j][1] * a3;
                e2 += (float)accl[f][j][2] * a3; e3 += (float)accl[f][j][3] * a3;
            }
            if (MODE == 0) {
                float2 b0 = *(const float2*)(bias + (long long)m0 * Ng + n);
                float2 b1 = *(const float2*)(bias + (long long)(m0 + 8) * Ng + n);
                e0 += b0.x * beta; e1 += b0.y * beta;
                e2 += b1.x * beta; e3 += b1.y * beta;
            } else {
                const float r0 = rscale[(long long)bz * Ng + n];
                const float r1 = rscale[(long long)bz * Ng + n + 1];
                e0 *= r0; e1 *= r1; e2 *= r0; e3 *= r1;
            }
            *(float2*)(Cf + (long long)m0 * Ng + n) = make_float2(e0, e1);
            *(float2*)(Cf + (long long)(m0 + 8) * Ng + n) = make_float2(e2, e3);
        }
    }
}

// ---------------------------------------------------------------------------
// fp16 HMMA GEMM (single pass) — TUPE bias chain only. (validated in R7/R8)
// ---------------------------------------------------------------------------
template<int OUTMODE>
__global__ void __launch_bounds__(256, 1)
hgemm(const __half* __restrict__ A, const __half* __restrict__ B,
      void* __restrict__ Cp, int Kt, int Ng)
{
    extern __shared__ __align__(128) char smem[];
    constexpr int RSTRIDE = 80;
    constexpr int TSZ = 128 * RSTRIDE;
    constexpr int STAGE = 2 * TSZ;

    const uint32_t sb = s2u(smem);
    const int tid = threadIdx.x;
    const int lane = tid & 31;
    const int wid = tid >> 5;
    const int warp_m = wid & 3;
    const int warp_n = wid >> 2;
    const int bm = blockIdx.y * 128, bn = blockIdx.x * 128;
    const int NC = Kt >> 5;

    auto load_chunk = [&](int c) {
        const uint32_t stg = sb + (c & 1) * STAGE;
        const long long kc = (long long)c << 5;
        #pragma unroll
        for (int it = 0; it < 4; it++) {
            const int idx = tid + it * 256;
            const int t4  = idx >> 9;
            const int r   = (idx >> 2) & 127;
            const int c16 = idx & 3;
            const __half* src = t4 ? B : A;
            const int rowg = (t4 ? bn : bm) + r;
            cpa16(stg + t4 * TSZ + r * RSTRIDE + c16 * 16,
                  src + (long long)rowg * Kt + kc + c16 * 8);
        }
        asm volatile("cp.async.commit_group;" ::: "memory");
    };

    float acc[2][8][4];
    #pragma unroll
    for (int f = 0; f < 2; f++)
        #pragma unroll
        for (int j = 0; j < 8; j++)
            #pragma unroll
            for (int e = 0; e < 4; e++) acc[f][j][e] = 0.f;

    load_chunk(0);
    const int lrow = lane & 15;
    const int lkof = (lane >> 4) * 16;

    for (int c = 0; c < NC; c++) {
        if (c + 1 < NC) {
            load_chunk(c + 1);
            asm volatile("cp.async.wait_group 1;" ::: "memory");
        } else {
            asm volatile("cp.async.wait_group 0;" ::: "memory");
        }
        __syncthreads();
        const uint32_t stg = sb + (c & 1) * STAGE;
        const uint32_t aOff = stg + (warp_m * 32 + lrow) * RSTRIDE + lkof;
        const uint32_t bOff = stg + TSZ + (warp_n * 64 + lrow) * RSTRIDE + lkof;
        #pragma unroll
        for (int ks = 0; ks < 2; ks++) {
            const uint32_t kb = ks * 32;
            uint32_t ah[2][4], bh[4][4];
            #pragma unroll
            for (int f = 0; f < 2; f++) LDSM4(ah[f], aOff + f * 16 * RSTRIDE + kb);
            #pragma unroll
            for (int g = 0; g < 4; g++) LDSM4(bh[g], bOff + g * 16 * RSTRIDE + kb);
            #pragma unroll
            for (int f = 0; f < 2; f++)
                #pragma unroll
                for (int g = 0; g < 4; g++) {
                    MMA_F16_F32(acc[f][2 * g + 0], ah[f], bh[g][0], bh[g][2]);
                    MMA_F16_F32(acc[f][2 * g + 1], ah[f], bh[g][1], bh[g][3]);
                }
        }
        __syncthreads();
    }

    const int qrow = lane >> 2;
    const int qcol = (lane & 3) * 2;
    #pragma unroll
    for (int f = 0; f < 2; f++) {
        const int m0 = bm + warp_m * 32 + f * 16 + qrow;
        #pragma unroll
        for (int j = 0; j < 8; j++) {
            const int n = bn + warp_n * 64 + j * 8 + qcol;
            if (OUTMODE == 0) {
                float* Cf = (float*)Cp;
                *(float2*)(Cf + (long long)m0 * Ng + n) = make_float2(acc[f][j][0], acc[f][j][1]);
                *(float2*)(Cf + (long long)(m0 + 8) * Ng + n) = make_float2(acc[f][j][2], acc[f][j][3]);
            } else {
                __half* Cb = (__half*)Cp;
                *(__half2*)(Cb + (long long)m0 * Ng + n) = __floats2half2_rn(acc[f][j][0], acc[f][j][1]);
                *(__half2*)(Cb + (long long)(m0 + 8) * Ng + n) = __floats2half2_rn(acc[f][j][2], acc[f][j][3]);
            }
        }
    }
}

// ----------------------- fp32 -> int8 two-digit split -----------------------
__device__ __forceinline__ void q2i8(float x, int8_t& h, int8_t& l) {
    float qs = x * SPLIT_SCALE;
    float qh = rintf(qs);
    qh = fminf(fmaxf(qh, -127.f), 127.f);
    float ql = rintf((qs - qh) * 254.f);
    ql = fminf(fmaxf(ql, -127.f), 127.f);
    h = (int8_t)(int)qh; l = (int8_t)(int)ql;
}

__global__ __launch_bounds__(256)
void split_i8(const float4* __restrict__ src, int8_t* __restrict__ hi,
              int8_t* __restrict__ lo, int n4)
{
    int i = blockIdx.x * 256 + threadIdx.x;
    if (i >= n4) return;
    float4 x = src[i];
    char4 h, l;
    int8_t a, b;
    q2i8(x.x, a, b); h.x = a; l.x = b;
    q2i8(x.y, a, b); h.y = a; l.y = b;
    q2i8(x.z, a, b); h.z = a; l.z = b;
    q2i8(x.w, a, b); h.w = a; l.w = b;
    ((char4*)hi)[i] = h;
    ((char4*)lo)[i] = l;
}

__global__ __launch_bounds__(256)
void split_h(const float4* __restrict__ src, __half* __restrict__ hi, int n4)
{
    int i = blockIdx.x * 256 + threadIdx.x;
    if (i >= n4) return;
    float4 x = src[i];
    ((__half2*)hi)[2 * i]     = __floats2half2_rn(x.x, x.y);
    ((__half2*)hi)[2 * i + 1] = __floats2half2_rn(x.z, x.w);
}

__global__ __launch_bounds__(256)
void tsplit_h(const float* __restrict__ src, __half* __restrict__ hi, int R, int C)
{
    __shared__ float tile[32][33];
    const int c0 = blockIdx.x * 32, r0 = blockIdx.y * 32;
    const int tx = threadIdx.x, ty = threadIdx.y;
    #pragma unroll
    for (int i = 0; i < 4; i++)
        tile[ty + i * 8][tx] = src[(long long)(r0 + ty + i * 8) * C + c0 + tx];
    __syncthreads();
    #pragma unroll
    for (int i = 0; i < 4; i++)
        hi[(long long)(c0 + ty + i * 8) * R + r0 + tx] = __float2half_rn(tile[tx][ty + i * 8]);
}

__global__ __launch_bounds__(256)
void tsplit_i8(const float* __restrict__ src, int8_t* __restrict__ hi,
               int8_t* __restrict__ lo, int R, int C, long long sStr, long long dStr)
{
    __shared__ float tile[32][33];
    src += (long long)blockIdx.z * sStr;
    const int c0 = blockIdx.x * 32, r0 = blockIdx.y * 32;
    const int tx = threadIdx.x, ty = threadIdx.y;
    #pragma unroll
    for (int i = 0; i < 4; i++)
        tile[ty + i * 8][tx] = src[(long long)(r0 + ty + i * 8) * C + c0 + tx];
    __syncthreads();
    #pragma unroll
    for (int i = 0; i < 4; i++) {
        int8_t h, l;
        q2i8(tile[tx][ty + i * 8], h, l);
        long long o = (long long)blockIdx.z * dStr + (long long)(c0 + ty + i * 8) * R + r0 + tx;
        hi[o] = h; lo[o] = l;
    }
}

// ------------------------------- softmax ------------------------------------
__global__ __launch_bounds__(256)
void softmax_kernel(const float* __restrict__ scores, float* __restrict__ attn_out,
                    int8_t* __restrict__ eh, int8_t* __restrict__ el,
                    float* __restrict__ rscale)
{
    const size_t row = blockIdx.x;
    const float* p = scores + row * SEQ;
    const int t = threadIdx.x;
    __shared__ float red[8];

    float v[8];
    float mx = -INFINITY;
    #pragma unroll
    for (int i = 0; i < 8; i++) { v[i] = p[t + i * 256]; mx = fmaxf(mx, v[i]); }
    #pragma unroll
    for (int o = 16; o; o >>= 1) mx = fmaxf(mx, __shfl_xor_sync(0xffffffffu, mx, o));
    if ((t & 31) == 0) red[t >> 5] = mx;
    __syncthreads();
    mx = red[0];
    #pragma unroll
    for (int w = 1; w < 8; w++) mx = fmaxf(mx, red[w]);
    __syncthreads();

    float s = 0.f;
    #pragma unroll
    for (int i = 0; i < 8; i++) { v[i] = __expf(v[i] - mx); s += v[i]; }
    #pragma unroll
    for (int o = 16; o; o >>= 1) s += __shfl_xor_sync(0xffffffffu, s, o);
    if ((t & 31) == 0) red[t >> 5] = s;
    __syncthreads();
    s = 0.f;
    #pragma unroll
    for (int w = 0; w < 8; w++) s += red[w];

    const float inv = 1.f / s;
    if (rscale && t == 0) rscale[row] = inv;
    #pragma unroll
    for (int i = 0; i < 8; i++) {
        const size_t idx = row * SEQ + t + i * 256;
        if (attn_out) attn_out[idx] = v[i] * inv;
        if (eh) {
            float es = v[i] * 127.f;
            float h = rintf(es);
            float l = rintf((es - h) * 254.f);
            l = fminf(fmaxf(l, -127.f), 127.f);
            eh[idx] = (int8_t)(int)h;
            el[idx] = (int8_t)(int)l;
        }
    }
}

// ---------------------------------------------------------------------------
extern "C" void kernel_launch(void* const* d_in, const int* in_sizes, int n_in,
                              void* d_out, int out_size)
{
    const float* q  = (const float*)d_in[0];
    const float* k  = (const float*)d_in[1];
    const float* v  = (const float*)d_in[2];
    const float* pe = (const float*)d_in[3];
    const float* Uq = (const float*)d_in[4];
    const float* Uk = (const float*)d_in[5];
    float* out = (float*)d_out;

    int8_t *qh, *ql, *kh, *kl, *vth, *vtl, *eh, *el;
    __half *pehi, *uqt, *ukt, *qpe, *kpe;
    float *bias, *scores, *rscale;
    cudaGetSymbolAddress((void**)&qh,  g_qh);   cudaGetSymbolAddress((void**)&ql,  g_ql);
    cudaGetSymbolAddress((void**)&kh,  g_kh);   cudaGetSymbolAddress((void**)&kl,  g_kl);
    cudaGetSymbolAddress((void**)&vth, g_vth);  cudaGetSymbolAddress((void**)&vtl, g_vtl);
    cudaGetSymbolAddress((void**)&eh,  g_eh);   cudaGetSymbolAddress((void**)&el,  g_el);
    cudaGetSymbolAddress((void**)&pehi, g_pehi);
    cudaGetSymbolAddress((void**)&uqt,  g_uqt); cudaGetSymbolAddress((void**)&ukt,  g_ukt);
    cudaGetSymbolAddress((void**)&qpe,  g_qpe); cudaGetSymbolAddress((void**)&kpe,  g_kpe);
    cudaGetSymbolAddress((void**)&bias, g_bias);
    cudaGetSymbolAddress((void**)&scores, g_scores);
    cudaGetSymbolAddress((void**)&rscale, g_rscale);

    const float invScale = 1.0f / 11.313708498984761f;  // 1/sqrt(2*64)

    const long long ctxElems  = (long long)NB * SEQ * DM;
    const long long attnElems = (long long)NB * SEQ * SEQ;
    float* ctxOut  = out;
    float* attnOut = nullptr;
    if ((long long)out_size == ctxElems + attnElems) {
        attnOut = out + ctxElems;
    } else if ((long long)out_size == attnElems) {
        attnOut = out; ctxOut = nullptr;
    }

    const int SMI = 2 * (2 * 128 * 80 + 2 * 64 * 80);   // 61440 B
    const int SMH = 2 * 2 * 128 * 80;                    // 40960 B
    cudaFuncSetAttribute(igemm<0, 1>, cudaFuncAttributeMaxDynamicSharedMemorySize, SMI);
    cudaFuncSetAttribute(igemm<1, 0>, cudaFuncAttributeMaxDynamicSharedMemorySize, SMI);
    cudaFuncSetAttribute(hgemm<0>, cudaFuncAttributeMaxDynamicSharedMemorySize, SMH);
    cudaFuncSetAttribute(hgemm<1>, cudaFuncAttributeMaxDynamicSharedMemorySize, SMH);

    // ---- quantize / convert inputs ----
    split_i8<<<(int)(NQ / 4 / 256), 256>>>((const float4*)q, qh, ql, (int)(NQ / 4));
    split_i8<<<(int)(NQ / 4 / 256), 256>>>((const float4*)k, kh, kl, (int)(NQ / 4));
    split_h<<<(int)(NP / 4 / 256), 256>>>((const float4*)pe, pehi, (int)(NP / 4));
    tsplit_h<<<dim3(DM / 32, DM / 32, 1), dim3(32, 8)>>>(Uq, uqt, DM, DM);
    tsplit_h<<<dim3(DM / 32, DM / 32, 1), dim3(32, 8)>>>(Uk, ukt, DM, DM);
    if (ctxOut)
        tsplit_i8<<<dim3(DM / 32, SEQ / 32, NB), dim3(32, 8)>>>(
            v, vth, vtl, SEQ, DM, (long long)SEQ * DM, (long long)SEQ * DM);

    // ---- TUPE bias chain (fp16) ----
    hgemm<1><<<dim3(DM / 128, SEQ / 128, 1), 256, SMH>>>(pehi, uqt, qpe, DM, DM);
    hgemm<1><<<dim3(DM / 128, SEQ / 128, 1), 256, SMH>>>(pehi, ukt, kpe, DM, DM);
    hgemm<0><<<dim3(SEQ / 128, SEQ / 128, 1), 256, SMH>>>(qpe, kpe, bias, DM, SEQ);

    // ---- scores = (q@k^T)*invScale + bias*invScale  (int8 two-digit + lolo) ----
    igemm<0, 1><<<dim3(SEQ / 64, SEQ / 128, NB), 256, SMI>>>(
        qh, ql, kh, kl, scores, bias, nullptr, DM, SEQ,
        (long long)SEQ * DM, (long long)SEQ * DM, (long long)SEQ * SEQ,
        INV_SPLIT2 * invScale, invScale);

    // ---- softmax (emits attn fp32, exp digits int8, per-row scales) ----
    softmax_kernel<<<NB * SEQ, 256>>>(scores, attnOut,
                                      ctxOut ? eh : nullptr, ctxOut ? el : nullptr,
                                      ctxOut ? rscale : nullptr);

    // ---- ctx^T = v^T @ attn^T (int8 two-digit, per-batch row scales) ----
    if (ctxOut)
        igemm<1, 0><<<dim3(SEQ / 64, DM / 128, NB), 256, SMI>>>(
            vth, vtl, eh, el, ctxOut, nullptr, rscale, SEQ, SEQ,
            (long long)SEQ * DM, (long long)SEQ * SEQ, (long long)SEQ * DM,
            (6.0f / 127.0f) / 127.0f, 0.f);
}

// round 10
// speedup vs baseline: 2.7248x; 2.7248x over previous
#include <cuda_runtime.h>
#include <cuda_fp16.h>
#include <math.h>
#include <stdint.h>

#define SEQ 2048
#define DM  1024
#define NB  4

static constexpr size_t NQ  = (size_t)NB * SEQ * DM;    //  8388608
static constexpr size_t NSS = (size_t)NB * SEQ * SEQ;   // 16777216
static constexpr size_t NP  = (size_t)SEQ * DM;         //  2097152
static constexpr size_t NU  = (size_t)DM * DM;          //  1048576

// ---- scratch (static device globals; no allocation) ----
__device__ __half g_qhi[NQ],  g_qlo[NQ];
__device__ __half g_khi[NQ],  g_klo[NQ];
__device__ __half g_vthi[NQ];
__device__ __half g_ahi[NSS];
__device__ __half g_pehi[NP];
__device__ __half g_uqt[NU],  g_ukt[NU];
__device__ __half g_qpe[NP],  g_kpe[NP];
__device__ float  g_bias[(size_t)SEQ * SEQ];
__device__ float  g_scores[NSS];

// ------------------------------- PTX helpers -------------------------------
__device__ __forceinline__ uint32_t s2u(const void* p) {
    uint32_t a;
    asm("{ .reg .u64 t; cvta.to.shared.u64 t, %1; cvt.u32.u64 %0, t; }"
        : "=r"(a) : "l"(p));
    return a;
}
__device__ __forceinline__ void cpa16(uint32_t dst, const void* src) {
    asm volatile("cp.async.cg.shared.global [%0], [%1], 16;" :: "r"(dst), "l"(src) : "memory");
}
#define LDSM4(r, addr) \
    asm volatile("ldmatrix.sync.aligned.m8n8.x4.shared.b16 {%0,%1,%2,%3}, [%4];" \
        : "=r"((r)[0]), "=r"((r)[1]), "=r"((r)[2]), "=r"((r)[3]) : "r"(addr))
#define MMA_F16_F32(d, a, b0, b1) \
    asm volatile("mma.sync.aligned.m16n8k16.row.col.f32.f16.f16.f32 " \
        "{%0,%1,%2,%3}, {%4,%5,%6,%7}, {%8,%9}, {%0,%1,%2,%3};" \
        : "+f"((d)[0]), "+f"((d)[1]), "+f"((d)[2]), "+f"((d)[3]) \
        : "r"((a)[0]), "r"((a)[1]), "r"((a)[2]), "r"((a)[3]), "r"(b0), "r"(b1))

// ---------------------------------------------------------------------------
// fp16 HMMA GEMM: C[M,N] = alpha * (sum_passes A_p @ B_p^T [+ bias])
//   A: [M,Kt] f16 K-major, B: [N,Kt] f16 K-major
//   PASSES==3: Ahi*Bhi + Ahi*Blo + Alo*Bhi      PASSES==1: Ahi*Bhi
//   OUTMODE: 0 = fp32 row-major (+bias, *alpha); 1 = fp16 row-major
//   CTA tile 128x128, BK=32, 256 threads (8 warps, warp tile 32x64),
//   2-stage cp.async pipeline, 80B-padded SMEM rows (conflict-free ldmatrix).
// ---------------------------------------------------------------------------
template<int PASSES, int OUTMODE>
__global__ void __launch_bounds__(256, 1)
hgemm(const __half* __restrict__ Ahi, const __half* __restrict__ Alo,
      const __half* __restrict__ Bhi, const __half* __restrict__ Blo,
      void* __restrict__ Cp, const float* __restrict__ bias, int Kt, int Ng,
      long long aStr, long long bStr, long long cStr, float alpha)
{
    extern __shared__ __align__(128) char smem[];
    constexpr int RSTRIDE = 80;                     // 32 f16 + 16B pad
    constexpr int TSZ = 128 * RSTRIDE;              // 10240 B per tile
    constexpr int NT  = (PASSES == 3) ? 4 : 2;      // tiles per stage
    constexpr int STAGE = NT * TSZ;

    const uint32_t sb = s2u(smem);
    const int tid = threadIdx.x;
    const int lane = tid & 31;
    const int wid = tid >> 5;
    const int warp_m = wid & 3;                      // 4 warps along M
    const int warp_n = wid >> 2;                     // 2 warps along N
    const int bm = blockIdx.y * 128, bn = blockIdx.x * 128, bz = blockIdx.z;
    const int NC = Kt >> 5;                          // chunks of BK=32

    const __half* Abase[2] = { Ahi + (long long)bz * aStr,
                               (PASSES == 3) ? Alo + (long long)bz * aStr : nullptr };
    const __half* Bbase[2] = { Bhi + (long long)bz * bStr,
                               (PASSES == 3) ? Blo + (long long)bz * bStr : nullptr };

    auto load_chunk = [&](int c) {
        const uint32_t stg = sb + (c & 1) * STAGE;
        const long long kc = (long long)c << 5;
        #pragma unroll
        for (int it = 0; it < NT * 2; it++) {
            const int idx = tid + it * 256;          // NT*512 chunks of 16B
            const int t4  = idx >> 9;                // tile id
            const int r   = (idx >> 2) & 127;        // row in tile
            const int c16 = idx & 3;                 // 16B chunk in row
            const __half* src;
            int rowg;
            if (PASSES == 3) {
                if (t4 < 2) { src = Abase[t4]; rowg = bm + r; }
                else        { src = Bbase[t4 - 2]; rowg = bn + r; }
            } else {
                if (t4 == 0) { src = Abase[0]; rowg = bm + r; }
                else         { src = Bbase[0]; rowg = bn + r; }
            }
            cpa16(stg + t4 * TSZ + r * RSTRIDE + c16 * 16,
                  src + (long long)rowg * Kt + kc + c16 * 8);
        }
        asm volatile("cp.async.commit_group;" ::: "memory");
    };

    float acc[2][8][4];
    #pragma unroll
    for (int f = 0; f < 2; f++)
        #pragma unroll
        for (int j = 0; j < 8; j++)
            #pragma unroll
            for (int e = 0; e < 4; e++) acc[f][j][e] = 0.f;

    load_chunk(0);

    const int lrow = lane & 15;
    const int lkof = (lane >> 4) * 16;               // bytes

    for (int c = 0; c < NC; c++) {
        if (c + 1 < NC) {
            load_chunk(c + 1);
            asm volatile("cp.async.wait_group 1;" ::: "memory");
        } else {
            asm volatile("cp.async.wait_group 0;" ::: "memory");
        }
        __syncthreads();
        const uint32_t stg = sb + (c & 1) * STAGE;
        const uint32_t aOff = stg + (warp_m * 32 + lrow) * RSTRIDE + lkof;
        const uint32_t bOff = stg + ((PASSES == 3 ? 2 : 1) * TSZ)
                            + (warp_n * 64 + lrow) * RSTRIDE + lkof;
        #pragma unroll
        for (int ks = 0; ks < 2; ks++) {
            const uint32_t kb = ks * 32;             // 16 elems = 32 bytes
            uint32_t ah[2][4], bh[4][4];
            #pragma unroll
            for (int f = 0; f < 2; f++) LDSM4(ah[f], aOff + f * 16 * RSTRIDE + kb);
            #pragma unroll
            for (int g = 0; g < 4; g++) LDSM4(bh[g], bOff + g * 16 * RSTRIDE + kb);
            if (PASSES == 3) {
                uint32_t al[2][4], bl[4][4];
                #pragma unroll
                for (int f = 0; f < 2; f++) LDSM4(al[f], aOff + TSZ + f * 16 * RSTRIDE + kb);
                #pragma unroll
                for (int g = 0; g < 4; g++) LDSM4(bl[g], bOff + TSZ + g * 16 * RSTRIDE + kb);
                #pragma unroll
                for (int f = 0; f < 2; f++)
                    #pragma unroll
                    for (int g = 0; g < 4; g++) {
                        MMA_F16_F32(acc[f][2 * g + 0], ah[f], bh[g][0], bh[g][2]);
                        MMA_F16_F32(acc[f][2 * g + 1], ah[f], bh[g][1], bh[g][3]);
                        MMA_F16_F32(acc[f][2 * g + 0], ah[f], bl[g][0], bl[g][2]);
                        MMA_F16_F32(acc[f][2 * g + 1], ah[f], bl[g][1], bl[g][3]);
                        MMA_F16_F32(acc[f][2 * g + 0], al[f], bh[g][0], bh[g][2]);
                        MMA_F16_F32(acc[f][2 * g + 1], al[f], bh[g][1], bh[g][3]);
                    }
            } else {
                #pragma unroll
                for (int f = 0; f < 2; f++)
                    #pragma unroll
                    for (int g = 0; g < 4; g++) {
                        MMA_F16_F32(acc[f][2 * g + 0], ah[f], bh[g][0], bh[g][2]);
                        MMA_F16_F32(acc[f][2 * g + 1], ah[f], bh[g][1], bh[g][3]);
                    }
            }
        }
        __syncthreads();
    }

    // ------------------------------- epilogue -------------------------------
    const int qrow = lane >> 2;
    const int qcol = (lane & 3) * 2;
    #pragma unroll
    for (int f = 0; f < 2; f++) {
        const int m0 = bm + warp_m * 32 + f * 16 + qrow;
        #pragma unroll
        for (int j = 0; j < 8; j++) {
            const int n = bn + warp_n * 64 + j * 8 + qcol;
            if (OUTMODE == 0) {
                float* Cf = (float*)Cp + (long long)bz * cStr;
                float2 v0 = make_float2(acc[f][j][0], acc[f][j][1]);
                float2 v1 = make_float2(acc[f][j][2], acc[f][j][3]);
                if (bias) {
                    float2 b0 = *(const float2*)(bias + (long long)m0 * Ng + n);
                    float2 b1 = *(const float2*)(bias + (long long)(m0 + 8) * Ng + n);
                    v0.x += b0.x; v0.y += b0.y; v1.x += b1.x; v1.y += b1.y;
                }
                v0.x *= alpha; v0.y *= alpha; v1.x *= alpha; v1.y *= alpha;
                *(float2*)(Cf + (long long)m0 * Ng + n) = v0;
                *(float2*)(Cf + (long long)(m0 + 8) * Ng + n) = v1;
            } else {
                __half* Cb = (__half*)Cp;
                *(__half2*)(Cb + (long long)m0 * Ng + n) = __floats2half2_rn(acc[f][j][0], acc[f][j][1]);
                *(__half2*)(Cb + (long long)(m0 + 8) * Ng + n) = __floats2half2_rn(acc[f][j][2], acc[f][j][3]);
            }
        }
    }
}

// ------------------------- fp32 -> fp16 hi/lo split -------------------------
template<int WLO>
__global__ __launch_bounds__(256)
void split_k(const float4* __restrict__ src, __half* __restrict__ hi,
             __half* __restrict__ lo, int n4)
{
    int i = blockIdx.x * 256 + threadIdx.x;
    if (i >= n4) return;
    float4 x = src[i];
    __half h0 = __float2half_rn(x.x), h1 = __float2half_rn(x.y);
    __half h2 = __float2half_rn(x.z), h3 = __float2half_rn(x.w);
    __half2 H0; H0.x = h0; H0.y = h1;
    __half2 H1; H1.x = h2; H1.y = h3;
    ((__half2*)hi)[2 * i]     = H0;
    ((__half2*)hi)[2 * i + 1] = H1;
    if (WLO) {
        __half2 L0, L1;
        L0.x = __float2half_rn(x.x - __half2float(h0));
        L0.y = __float2half_rn(x.y - __half2float(h1));
        L1.x = __float2half_rn(x.z - __half2float(h2));
        L1.y = __float2half_rn(x.w - __half2float(h3));
        ((__half2*)lo)[2 * i]     = L0;
        ((__half2*)lo)[2 * i + 1] = L1;
    }
}

// ------------------- transpose + convert: dst[c][r] = src[r][c] -------------
__global__ __launch_bounds__(256)
void tsplit_k(const float* __restrict__ src, __half* __restrict__ hi,
              int R, int C, long long sStr, long long dStr)
{
    __shared__ float tile[32][33];
    src += (long long)blockIdx.z * sStr;
    const int c0 = blockIdx.x * 32, r0 = blockIdx.y * 32;
    const int tx = threadIdx.x, ty = threadIdx.y;   // block (32,8)
    #pragma unroll
    for (int i = 0; i < 4; i++)
        tile[ty + i * 8][tx] = src[(long long)(r0 + ty + i * 8) * C + c0 + tx];
    __syncthreads();
    #pragma unroll
    for (int i = 0; i < 4; i++) {
        long long o = (long long)blockIdx.z * dStr + (long long)(c0 + ty + i * 8) * R + r0 + tx;
        hi[o] = __float2half_rn(tile[tx][ty + i * 8]);
    }
}

// ------------------------------- softmax ------------------------------------
__global__ __launch_bounds__(256)
void softmax_kernel(const float* __restrict__ scores, float* __restrict__ attn_out,
                    __half* __restrict__ ahi)
{
    const size_t row = blockIdx.x;
    const float* p = scores + row * SEQ;
    const int t = threadIdx.x;
    __shared__ float red[8];

    float v[8];
    float mx = -INFINITY;
    #pragma unroll
    for (int i = 0; i < 8; i++) { v[i] = p[t + i * 256]; mx = fmaxf(mx, v[i]); }
    #pragma unroll
    for (int o = 16; o; o >>= 1) mx = fmaxf(mx, __shfl_xor_sync(0xffffffffu, mx, o));
    if ((t & 31) == 0) red[t >> 5] = mx;
    __syncthreads();
    mx = red[0];
    #pragma unroll
    for (int w = 1; w < 8; w++) mx = fmaxf(mx, red[w]);
    __syncthreads();

    float s = 0.f;
    #pragma unroll
    for (int i = 0; i < 8; i++) { v[i] = __expf(v[i] - mx); s += v[i]; }
    #pragma unroll
    for (int o = 16; o; o >>= 1) s += __shfl_xor_sync(0xffffffffu, s, o);
    if ((t & 31) == 0) red[t >> 5] = s;
    __syncthreads();
    s = 0.f;
    #pragma unroll
    for (int w = 0; w < 8; w++) s += red[w];

    const float inv = 1.f / s;
    #pragma unroll
    for (int i = 0; i < 8; i++) {
        const float a = v[i] * inv;
        const size_t idx = row * SEQ + t + i * 256;
        if (attn_out) attn_out[idx] = a;
        if (ahi) ahi[idx] = __float2half_rn(a);
    }
}

// ---------------------------------------------------------------------------
extern "C" void kernel_launch(void* const* d_in, const int* in_sizes, int n_in,
                              void* d_out, int out_size)
{
    const float* q  = (const float*)d_in[0];
    const float* k  = (const float*)d_in[1];
    const float* v  = (const float*)d_in[2];
    const float* pe = (const float*)d_in[3];
    const float* Uq = (const float*)d_in[4];
    const float* Uk = (const float*)d_in[5];
    float* out = (float*)d_out;

    __half *qhi, *qlo, *khi, *klo, *vthi, *ahi;
    __half *pehi, *uqt, *ukt, *qpe, *kpe;
    float *bias, *scores;
    cudaGetSymbolAddress((void**)&qhi,  g_qhi);   cudaGetSymbolAddress((void**)&qlo,  g_qlo);
    cudaGetSymbolAddress((void**)&khi,  g_khi);   cudaGetSymbolAddress((void**)&klo,  g_klo);
    cudaGetSymbolAddress((void**)&vthi, g_vthi);  cudaGetSymbolAddress((void**)&ahi,  g_ahi);
    cudaGetSymbolAddress((void**)&pehi, g_pehi);
    cudaGetSymbolAddress((void**)&uqt,  g_uqt);   cudaGetSymbolAddress((void**)&ukt,  g_ukt);
    cudaGetSymbolAddress((void**)&qpe,  g_qpe);   cudaGetSymbolAddress((void**)&kpe,  g_kpe);
    cudaGetSymbolAddress((void**)&bias, g_bias);  cudaGetSymbolAddress((void**)&scores, g_scores);

    const float invScale = 1.0f / 11.313708498984761f;  // 1/sqrt(2*64)

    const long long ctxElems  = (long long)NB * SEQ * DM;
    const long long attnElems = (long long)NB * SEQ * SEQ;
    float* ctxOut  = out;
    float* attnOut = nullptr;
    if ((long long)out_size == ctxElems + attnElems) {
        attnOut = out + ctxElems;
    } else if ((long long)out_size == attnElems) {
        attnOut = out; ctxOut = nullptr;
    }

    const int SM3 = 2 * 4 * 128 * 80;   // 81920 B
    const int SM1 = 2 * 2 * 128 * 80;   // 40960 B
    cudaFuncSetAttribute(hgemm<3, 0>, cudaFuncAttributeMaxDynamicSharedMemorySize, SM3);
    cudaFuncSetAttribute(hgemm<1, 0>, cudaFuncAttributeMaxDynamicSharedMemorySize, SM1);
    cudaFuncSetAttribute(hgemm<1, 1>, cudaFuncAttributeMaxDynamicSharedMemorySize, SM1);

    // ---- splits ----
    split_k<1><<<(int)(NQ / 4 / 256), 256>>>((const float4*)q, qhi, qlo, (int)(NQ / 4));
    split_k<1><<<(int)(NQ / 4 / 256), 256>>>((const float4*)k, khi, klo, (int)(NQ / 4));
    split_k<0><<<(int)(NP / 4 / 256), 256>>>((const float4*)pe, pehi, nullptr, (int)(NP / 4));
    tsplit_k<<<dim3(DM / 32, DM / 32, 1), dim3(32, 8)>>>(Uq, uqt, DM, DM, 0, 0);
    tsplit_k<<<dim3(DM / 32, DM / 32, 1), dim3(32, 8)>>>(Uk, ukt, DM, DM, 0, 0);
    if (ctxOut)
        tsplit_k<<<dim3(DM / 32, SEQ / 32, NB), dim3(32, 8)>>>(
            v, vthi, SEQ, DM, (long long)SEQ * DM, (long long)SEQ * DM);

    // ---- TUPE bias chain (single-pass fp16) ----
    hgemm<1, 1><<<dim3(DM / 128, SEQ / 128, 1), 256, SM1>>>(
        pehi, nullptr, uqt, nullptr, qpe, nullptr, DM, DM, 0, 0, 0, 1.f);
    hgemm<1, 1><<<dim3(DM / 128, SEQ / 128, 1), 256, SM1>>>(
        pehi, nullptr, ukt, nullptr, kpe, nullptr, DM, DM, 0, 0, 0, 1.f);
    hgemm<1, 0><<<dim3(SEQ / 128, SEQ / 128, 1), 256, SM1>>>(
        qpe, nullptr, kpe, nullptr, bias, nullptr, DM, SEQ, 0, 0, 0, 1.f);

    // ---- scores = (q@k^T + bias) * invScale  (3-pass fp16) ----
    hgemm<3, 0><<<dim3(SEQ / 128, SEQ / 128, NB), 256, SM3>>>(
        qhi, qlo, khi, klo, scores, bias, DM, SEQ,
        (long long)SEQ * DM, (long long)SEQ * DM, (long long)SEQ * SEQ, invScale);

    // ---- softmax (emits attn fp32 and/or fp16) ----
    softmax_kernel<<<NB * SEQ, 256>>>(scores, attnOut, ctxOut ? ahi : nullptr);

    // ---- ctx^T = v^T @ attn^T  (SINGLE-pass fp16 — error self-normalizing) ----
    if (ctxOut)
        hgemm<1, 0><<<dim3(SEQ / 128, DM / 128, NB), 256, SM1>>>(
            vthi, nullptr, ahi, nullptr, ctxOut, nullptr, SEQ, SEQ,
            (long long)SEQ * DM, (long long)SEQ * SEQ, (long long)SEQ * DM, 1.f);
}